// round 14
// baseline (speedup 1.0000x reference)
#include <cuda_runtime.h>
#include <math.h>

#define NN   1024
#define RANK 64
#define MM   1024
#define FCH  32    // f per block (16 packed pairs)
#define NSL  32    // n-slice per block
#define NTH  128   // threads per block (4 r-quarters x 32 n)
#define RQ   (RANK / 4)   // r's per thread = 16

// Scratch
__device__ float2 d_Hf[RANK * MM];     // FFT(softplus(H)), [r][f]
__device__ float4 d_prep[RANK * NN];   // (wp, theta, cos th, sin th), [r][n]

typedef unsigned long long u64;

__device__ __forceinline__ u64 pack2(float lo, float hi) {
    u64 r; asm("mov.b64 %0, {%1, %2};" : "=l"(r) : "f"(lo), "f"(hi)); return r;
}
__device__ __forceinline__ u64 bcast2(float x) { return pack2(x, x); }
__device__ __forceinline__ void unpack2(u64 v, float& lo, float& hi) {
    asm("mov.b64 {%0, %1}, %2;" : "=f"(lo), "=f"(hi) : "l"(v));
}
__device__ __forceinline__ u64 fma2(u64 a, u64 b, u64 c) {
    u64 d; asm("fma.rn.f32x2 %0, %1, %2, %3;" : "=l"(d) : "l"(a), "l"(b), "l"(c)); return d;
}
__device__ __forceinline__ u64 add2(u64 a, u64 b) {
    u64 d; asm("add.rn.f32x2 %0, %1, %2;" : "=l"(d) : "l"(a), "l"(b)); return d;
}

// ---------------------------------------------------------------------------
// Fused aux kernel (256 threads/block):
//   blocks 0..63   : 1024-pt RADIX-4 DIT FFT of softplus(H[r,:]) (5 stages)
//   blocks 64..127 : prep (softplus(W), theta, cos, sin) -> [r][n]
// ---------------------------------------------------------------------------
__global__ void __launch_bounds__(256) aux_kernel(
    const float* __restrict__ H, int nH,
    const float* __restrict__ W,
    const float* __restrict__ tau, int nWT)
{
    if (blockIdx.x >= RANK) {
        int base = (blockIdx.x - RANK) * 1024;
#pragma unroll
        for (int k = 0; k < 4; k++) {
            int i = base + k * 256 + threadIdx.x;
            float wv = (i < nWT) ? W[i]   : 0.0f;
            float tv = (i < nWT) ? tau[i] : 0.0f;
            int n = i >> 6;           // / RANK
            int r = i & (RANK - 1);
            float wp = __logf(1.0f + __expf(wv));
            float th = (float)(2.0 * M_PI / (double)MM) * tv;
            float s1, c1;
            __sincosf(th, &s1, &c1);
            d_prep[r * NN + n] = make_float4(wp, th, c1, s1);
        }
        return;
    }

    __shared__ float re[MM];
    __shared__ float im[MM];
    int r = blockIdx.x;

    // Load with softplus, base-4 digit-reversed placement.
    for (int i = threadIdx.x; i < MM; i += 256) {
        int src = r * MM + i;
        float x = (src < nH) ? H[src] : 0.0f;
        float v = __logf(1.0f + __expf(x));
        int dr = 0, t = i;
#pragma unroll
        for (int d = 0; d < 5; d++) { dr = (dr << 2) | (t & 3); t >>= 2; }
        re[dr] = v;
        im[dr] = 0.0f;
    }
    __syncthreads();

    // 5 radix-4 stages; 256 butterflies/stage = 1 per thread.
    int q = 1;
#pragma unroll
    for (int s = 0; s < 5; s++) {
        int m = q << 2;
        int k = threadIdx.x;
        int gi = k / q;
        int j  = k - gi * q;
        int i0 = gi * m + j;
        int i1 = i0 + q, i2 = i1 + q, i3 = i2 + q;

        float ang = (-6.2831853071795865f / (float)m) * (float)j;
        float c1, s1, c2, s2;
        __sincosf(ang, &s1, &c1);
        __sincosf(2.0f * ang, &s2, &c2);
        float c3 = c1 * c2 - s1 * s2;
        float s3 = s1 * c2 + c1 * s2;

        float ar = re[i0], ai = im[i0];
        float br = re[i1], bi = im[i1];
        float cr = re[i2], ci = im[i2];
        float dr_ = re[i3], di = im[i3];

        float tbr = br * c1 - bi * s1, tbi = bi * c1 + br * s1;
        float tcr = cr * c2 - ci * s2, tci = ci * c2 + cr * s2;
        float tdr = dr_ * c3 - di * s3, tdi = di * c3 + dr_ * s3;

        float e0r = ar + tcr,  e0i = ai + tci;
        float e1r = ar - tcr,  e1i = ai - tci;
        float e2r = tbr + tdr, e2i = tbi + tdi;
        float e3r = tbr - tdr, e3i = tbi - tdi;

        re[i0] = e0r + e2r;  im[i0] = e0i + e2i;
        re[i1] = e1r + e3i;  im[i1] = e1i - e3r;
        re[i2] = e0r - e2r;  im[i2] = e0i - e2i;
        re[i3] = e1r - e3i;  im[i3] = e1i + e3r;
        __syncthreads();
        q = m;
    }

    for (int i = threadIdx.x; i < MM; i += 256)
        d_Hf[r * MM + i] = make_float2(re[i], im[i]);
}

// ---------------------------------------------------------------------------
// out[n,f] = Re( sum_r wp e^{-i theta f} Hf[r,f] ).
// Sign-transformed Chebyshev recurrence (pure FMA chain), f32x2-packed.
// FCH=32 (seed setup amortized over 16 t-steps), 4-way r-split, 128-thread
// blocks, grid 1024 (balanced waves). We sit near the fma-pipe rt=2 ceiling;
// this round removes ~10% of fma-pipe ops.
// ---------------------------------------------------------------------------
__global__ void __launch_bounds__(NTH, 6) main_kernel(float* __restrict__ outf,
                                                      int capf) {
    __shared__ ulonglong2 g[RANK][FCH / 2];  // .x = sg*(Re,Re'), .y = sg*(-Im,-Im')
    __shared__ u64 comb[3][NSL][FCH / 2];    // partials from r-quarters 1..3

    int c  = blockIdx.x;
    int f0 = c * FCH;
    int t  = threadIdx.x;
    int ln = t & (NSL - 1);          // n within slice
    int rq = t >> 5;                 // r-quarter: 0..3
    int n  = blockIdx.y * NSL + ln;

    for (int e = t; e < RANK * (FCH / 2); e += NTH) {
        int rr = e >> 4;             // / 16
        int tt = e & 15;
        float4 ab = *(const float4*)&d_Hf[rr * MM + f0 + 2 * tt];
        float sg = (tt & 2) ? -1.0f : 1.0f;          // sigma_t = (-1)^(t/2)
        g[rr][tt] = make_ulonglong2(pack2(sg * ab.x, sg * ab.z),
                                    pack2(-sg * ab.y, -sg * ab.w));
    }
    __syncthreads();

    u64 acc[FCH / 2];
#pragma unroll
    for (int q = 0; q < FCH / 2; q++) acc[q] = 0ull;

    const float f0f = (float)f0;
    const int rbeg = rq * RQ;
    const float4* prep = &d_prep[rbeg * NN + n];

    // 2-deep prefetch pipeline over this thread's 16 r's.
    float4 pb[2];
#pragma unroll
    for (int k = 0; k < 2; k++) pb[k] = prep[k * NN];

    for (int r0 = 0; r0 < RQ; r0 += 2) {
        float4 pn[2];
        if (r0 + 2 < RQ) {
#pragma unroll
            for (int k = 0; k < 2; k++) pn[k] = prep[(r0 + 2 + k) * NN];
        }

#pragma unroll
        for (int k = 0; k < 2; k++) {
            int r = rbeg + r0 + k;
            float wp = pb[k].x, th = pb[k].y, c1 = pb[k].z, s1 = pb[k].w;

            float s0, c0;
            __sincosf(th * f0f, &s0, &c0);          // start angle (<= ~6.2 rad)

            float tc = c1 + c1;                                // 2 cos theta
            float pr0 = wp * c0, pi0 = -wp * s0;               // p(f0)
            float pr1  = fmaf(pr0, c1,  pi0 * s1);             // p(f0+1)
            float pi1  = fmaf(pi0, c1, -pr0 * s1);
            float prm1 = fmaf(pr0, c1, -pi0 * s1);             // p(f0-1)
            float pim1 = fmaf(pi0, c1,  pr0 * s1);
            float prm2 = fmaf(tc, prm1, -pr0);                 // p(f0-2) Cheb
            float pim2 = fmaf(tc, pim1, -pi0);
            float K    = fmaf(tc, tc, -2.0f);                  // 2 cos 2theta

            u64 Kp = bcast2(K), Kn = bcast2(-K);
            u64 qr_c = pack2(pr0, pr1),     qi_c = pack2(pi0, pi1);
            u64 qr_p = pack2(-prm2, -prm1), qi_p = pack2(-pim2, -pim1);

#pragma unroll
            for (int tt = 0; tt < FCH / 2; tt++) {
                ulonglong2 gv = g[r][tt];           // one LDS.128 (broadcast)
                acc[tt] = fma2(qr_c, gv.x, acc[tt]);
                acc[tt] = fma2(qi_c, gv.y, acc[tt]);
                u64 Kt = (tt & 1) ? Kn : Kp;
                u64 nr = fma2(Kt, qr_c, qr_p);
                u64 ni = fma2(Kt, qi_c, qi_p);
                qr_p = qr_c;  qr_c = nr;
                qi_p = qi_c;  qi_c = ni;
            }
        }

#pragma unroll
        for (int k = 0; k < 2; k++) pb[k] = pn[k];
    }

    // Combine the four r-quarters.
    if (rq) {
#pragma unroll
        for (int q = 0; q < FCH / 2; q++) comb[rq - 1][ln][q] = acc[q];
    }
    __syncthreads();
    if (rq) return;

#pragma unroll
    for (int q = 0; q < FCH / 2; q++) {
        acc[q] = add2(acc[q], comb[0][ln][q]);
        acc[q] = add2(acc[q], add2(comb[1][ln][q], comb[2][ln][q]));
    }

    int base = n * MM + f0;
    if (base + FCH <= capf) {
        float4* o4 = (float4*)(outf + base);       // 128B aligned
#pragma unroll
        for (int v = 0; v < FCH / 4; v++) {
            float a0, a1, b0, b1;
            unpack2(acc[2 * v],     a0, a1);
            unpack2(acc[2 * v + 1], b0, b1);
            o4[v] = make_float4(a0, a1, b0, b1);
        }
    } else {
#pragma unroll
        for (int q = 0; q < FCH / 2; q++) {
            float lo, hi;
            unpack2(acc[q], lo, hi);
            int o = base + 2 * q;
            if (o < capf)     outf[o]     = lo;
            if (o + 1 < capf) outf[o + 1] = hi;
        }
    }
}

// ---------------------------------------------------------------------------
extern "C" void kernel_launch(void* const* d_in, const int* in_sizes, int n_in,
                              void* d_out, int out_size) {
    if (n_in < 3) return;
    const float* W   = (const float*)d_in[0];
    const float* H   = (const float*)d_in[1];
    const float* tau = (const float*)d_in[2];
    float* outf = (float*)d_out;

    int nWT = in_sizes[0] < in_sizes[2] ? in_sizes[0] : in_sizes[2];
    aux_kernel<<<2 * RANK, 256>>>(H, in_sizes[1], W, tau, nWT);
    main_kernel<<<dim3(MM / FCH, NN / NSL), NTH>>>(outf, out_size);
}

// round 15
// speedup vs baseline: 1.1242x; 1.1242x over previous
#include <cuda_runtime.h>
#include <math.h>

#define NN   1024
#define RANK 64
#define MM   1024
#define FCH  16    // f per block (8 packed pairs)
#define NSL  64    // n-slice per block
#define NTH  256   // threads per block (4 r-quarters x 64 n)
#define RQ   (RANK / 4)   // r's per thread = 16
#define NPROD (2 * RANK)  // producer blocks (64 FFT + 64 prep)

// Scratch
__device__ float2 d_Hf[RANK * MM];     // FFT(softplus(H)), [r][f]
__device__ float4 d_prep[RANK * NN];   // (wp, theta, cos th, sin th), [r][n]
__device__ int    d_done;              // producer-completion counter (memset per launch)

typedef unsigned long long u64;

__device__ __forceinline__ u64 pack2(float lo, float hi) {
    u64 r; asm("mov.b64 %0, {%1, %2};" : "=l"(r) : "f"(lo), "f"(hi)); return r;
}
__device__ __forceinline__ u64 bcast2(float x) { return pack2(x, x); }
__device__ __forceinline__ void unpack2(u64 v, float& lo, float& hi) {
    asm("mov.b64 {%0, %1}, %2;" : "=f"(lo), "=f"(hi) : "l"(v));
}
__device__ __forceinline__ u64 fma2(u64 a, u64 b, u64 c) {
    u64 d; asm("fma.rn.f32x2 %0, %1, %2, %3;" : "=l"(d) : "l"(a), "l"(b), "l"(c)); return d;
}
__device__ __forceinline__ u64 add2(u64 a, u64 b) {
    u64 d; asm("add.rn.f32x2 %0, %1, %2;" : "=l"(d) : "l"(a), "l"(b)); return d;
}

// ---------------------------------------------------------------------------
// ONE fused launch. Blocks 0..63: radix-4 FFT of softplus(H[r]).
// Blocks 64..127: prep. Blocks 128..1151: main (spin until producers done).
// Shared memory manually overlaid: FFT uses 8KB, main uses 20KB.
// ---------------------------------------------------------------------------
__global__ void __launch_bounds__(NTH, 4) fused_kernel(
    const float* __restrict__ H, int nH,
    const float* __restrict__ W,
    const float* __restrict__ tau, int nWT,
    float* __restrict__ outf, int capf)
{
    __shared__ __align__(16) char smraw[20480];
    int bid = blockIdx.x;
    int t   = threadIdx.x;

    if (bid < RANK) {
        // ---------------- FFT producer ----------------
        float* re = (float*)smraw;
        float* im = (float*)(smraw + 4096);
        int r = bid;

        for (int i = t; i < MM; i += NTH) {
            int src = r * MM + i;
            float x = (src < nH) ? H[src] : 0.0f;
            float v = __logf(1.0f + __expf(x));
            int dr = 0, tt = i;
#pragma unroll
            for (int d = 0; d < 5; d++) { dr = (dr << 2) | (tt & 3); tt >>= 2; }
            re[dr] = v;
            im[dr] = 0.0f;
        }
        __syncthreads();

        int q = 1;
#pragma unroll
        for (int s = 0; s < 5; s++) {
            int m = q << 2;
            int k = t;
            int gi = k / q;
            int j  = k - gi * q;
            int i0 = gi * m + j;
            int i1 = i0 + q, i2 = i1 + q, i3 = i2 + q;

            float ang = (-6.2831853071795865f / (float)m) * (float)j;
            float c1, s1, c2, s2;
            __sincosf(ang, &s1, &c1);
            __sincosf(2.0f * ang, &s2, &c2);
            float c3 = c1 * c2 - s1 * s2;
            float s3 = s1 * c2 + c1 * s2;

            float ar = re[i0], ai = im[i0];
            float br = re[i1], bi = im[i1];
            float cr = re[i2], ci = im[i2];
            float dr_ = re[i3], di = im[i3];

            float tbr = br * c1 - bi * s1, tbi = bi * c1 + br * s1;
            float tcr = cr * c2 - ci * s2, tci = ci * c2 + cr * s2;
            float tdr = dr_ * c3 - di * s3, tdi = di * c3 + dr_ * s3;

            float e0r = ar + tcr,  e0i = ai + tci;
            float e1r = ar - tcr,  e1i = ai - tci;
            float e2r = tbr + tdr, e2i = tbi + tdi;
            float e3r = tbr - tdr, e3i = tbi - tdi;

            re[i0] = e0r + e2r;  im[i0] = e0i + e2i;
            re[i1] = e1r + e3i;  im[i1] = e1i - e3r;
            re[i2] = e0r - e2r;  im[i2] = e0i - e2i;
            re[i3] = e1r - e3i;  im[i3] = e1i + e3r;
            __syncthreads();
            q = m;
        }

        for (int i = t; i < MM; i += NTH)
            d_Hf[r * MM + i] = make_float2(re[i], im[i]);
        __syncthreads();
        if (t == 0) { __threadfence(); atomicAdd(&d_done, 1); }
        return;
    }

    if (bid < NPROD) {
        // ---------------- prep producer ----------------
        int base = (bid - RANK) * 1024;
#pragma unroll
        for (int k = 0; k < 4; k++) {
            int i = base + k * NTH + t;
            float wv = (i < nWT) ? W[i]   : 0.0f;
            float tv = (i < nWT) ? tau[i] : 0.0f;
            int n = i >> 6;           // / RANK
            int r = i & (RANK - 1);
            float wp = __logf(1.0f + __expf(wv));
            float th = (float)(2.0 * M_PI / (double)MM) * tv;
            float s1, c1;
            __sincosf(th, &s1, &c1);
            d_prep[r * NN + n] = make_float4(wp, th, c1, s1);
        }
        __syncthreads();
        if (t == 0) { __threadfence(); atomicAdd(&d_done, 1); }
        return;
    }

    // ---------------- main consumer (R13 configuration) ----------------
    ulonglong2 (*g)[FCH / 2]      = (ulonglong2 (*)[FCH / 2])smraw;
    u64 (*comb)[NSL][FCH / 2]     = (u64 (*)[NSL][FCH / 2])(smraw + 8192);

    int mb = bid - NPROD;
    int c  = mb & 63;                // chunk index (MM/FCH = 64)
    int f0 = c * FCH;
    int ln = t & (NSL - 1);          // n within slice
    int rq = t >> 6;                 // r-quarter: 0..3
    int n  = (mb >> 6) * NSL + ln;

    // Wait for all producers.
    if (t == 0) {
        while (atomicAdd(&d_done, 0) < NPROD) __nanosleep(128);
        __threadfence();
    }
    __syncthreads();

    for (int e = t; e < RANK * (FCH / 2); e += NTH) {
        int rr = e >> 3;             // / 8
        int tt = e & 7;
        float4 ab = *(const float4*)&d_Hf[rr * MM + f0 + 2 * tt];
        float sg = (tt & 2) ? -1.0f : 1.0f;          // sigma_t = (-1)^(t/2)
        g[rr][tt] = make_ulonglong2(pack2(sg * ab.x, sg * ab.z),
                                    pack2(-sg * ab.y, -sg * ab.w));
    }
    __syncthreads();

    u64 acc[FCH / 2];
#pragma unroll
    for (int q = 0; q < FCH / 2; q++) acc[q] = 0ull;

    const float f0f = (float)f0;
    const int rbeg = rq * RQ;
    const float4* prep = &d_prep[rbeg * NN + n];

    float4 pb[2];
#pragma unroll
    for (int k = 0; k < 2; k++) pb[k] = prep[k * NN];

    for (int r0 = 0; r0 < RQ; r0 += 2) {
        float4 pn[2];
        if (r0 + 2 < RQ) {
#pragma unroll
            for (int k = 0; k < 2; k++) pn[k] = prep[(r0 + 2 + k) * NN];
        }

#pragma unroll
        for (int k = 0; k < 2; k++) {
            int r = rbeg + r0 + k;
            float wp = pb[k].x, th = pb[k].y, c1 = pb[k].z, s1 = pb[k].w;

            float s0, c0;
            __sincosf(th * f0f, &s0, &c0);

            float pr0 = wp * c0, pi0 = -wp * s0;              // p(f0)
            float pr1  = fmaf(pr0, c1,  pi0 * s1);            // p(f0+1)
            float pi1  = fmaf(pi0, c1, -pr0 * s1);
            float prm1 = fmaf(pr0, c1, -pi0 * s1);            // p(f0-1)
            float pim1 = fmaf(pi0, c1,  pr0 * s1);
            float prm2 = fmaf(prm1, c1, -pim1 * s1);          // p(f0-2)
            float pim2 = fmaf(pim1, c1,  prm1 * s1);
            float K    = fmaf(4.0f * c1, c1, -2.0f);          // 2 cos 2theta

            u64 Kp = bcast2(K), Kn = bcast2(-K);
            u64 qr_c = pack2(pr0, pr1),     qi_c = pack2(pi0, pi1);
            u64 qr_p = pack2(-prm2, -prm1), qi_p = pack2(-pim2, -pim1);

#pragma unroll
            for (int tt = 0; tt < FCH / 2; tt++) {
                ulonglong2 gv = g[r][tt];
                acc[tt] = fma2(qr_c, gv.x, acc[tt]);
                acc[tt] = fma2(qi_c, gv.y, acc[tt]);
                u64 Kt = (tt & 1) ? Kn : Kp;
                u64 nr = fma2(Kt, qr_c, qr_p);
                u64 ni = fma2(Kt, qi_c, qi_p);
                qr_p = qr_c;  qr_c = nr;
                qi_p = qi_c;  qi_c = ni;
            }
        }

#pragma unroll
        for (int k = 0; k < 2; k++) pb[k] = pn[k];
    }

    if (rq) {
#pragma unroll
        for (int q = 0; q < FCH / 2; q++) comb[rq - 1][ln][q] = acc[q];
    }
    __syncthreads();
    if (rq) return;

#pragma unroll
    for (int q = 0; q < FCH / 2; q++) {
        acc[q] = add2(acc[q], comb[0][ln][q]);
        acc[q] = add2(acc[q], add2(comb[1][ln][q], comb[2][ln][q]));
    }

    int base = n * MM + f0;
    if (base + FCH <= capf) {
        float4* o4 = (float4*)(outf + base);
#pragma unroll
        for (int v = 0; v < FCH / 4; v++) {
            float a0, a1, b0, b1;
            unpack2(acc[2 * v],     a0, a1);
            unpack2(acc[2 * v + 1], b0, b1);
            o4[v] = make_float4(a0, a1, b0, b1);
        }
    } else {
#pragma unroll
        for (int q = 0; q < FCH / 2; q++) {
            float lo, hi;
            unpack2(acc[q], lo, hi);
            int o = base + 2 * q;
            if (o < capf)     outf[o]     = lo;
            if (o + 1 < capf) outf[o + 1] = hi;
        }
    }
}

// ---------------------------------------------------------------------------
extern "C" void kernel_launch(void* const* d_in, const int* in_sizes, int n_in,
                              void* d_out, int out_size) {
    if (n_in < 3) return;
    const float* W   = (const float*)d_in[0];
    const float* H   = (const float*)d_in[1];
    const float* tau = (const float*)d_in[2];
    float* outf = (float*)d_out;

    int nWT = in_sizes[0] < in_sizes[2] ? in_sizes[0] : in_sizes[2];

    void* daddr = nullptr;
    cudaGetSymbolAddress(&daddr, d_done);
    cudaMemsetAsync(daddr, 0, sizeof(int));   // stream-ordered flag reset

    fused_kernel<<<NPROD + (MM / FCH) * (NN / NSL), NTH>>>(
        H, in_sizes[1], W, tau, nWT, outf, out_size);
}

// round 16
// speedup vs baseline: 1.1636x; 1.0350x over previous
#include <cuda_runtime.h>
#include <math.h>

#define NN   1024
#define RANK 64
#define MM   1024
#define FCH  16    // f per block (8 packed pairs)
#define NSL  64    // n-slice per block
#define NTH  256   // threads per block (4 r-quarters x 64 n)
#define RQ   (RANK / 4)   // r's per thread = 16

// Scratch
__device__ float2 d_Hf[RANK * MM];     // FFT(softplus(H)), [r][f]
__device__ float4 d_prep[RANK * NN];   // (wp, theta, cos th, sin th), [r][n]

typedef unsigned long long u64;

__device__ __forceinline__ u64 pack2(float lo, float hi) {
    u64 r; asm("mov.b64 %0, {%1, %2};" : "=l"(r) : "f"(lo), "f"(hi)); return r;
}
__device__ __forceinline__ u64 bcast2(float x) { return pack2(x, x); }
__device__ __forceinline__ void unpack2(u64 v, float& lo, float& hi) {
    asm("mov.b64 {%0, %1}, %2;" : "=f"(lo), "=f"(hi) : "l"(v));
}
__device__ __forceinline__ u64 fma2(u64 a, u64 b, u64 c) {
    u64 d; asm("fma.rn.f32x2 %0, %1, %2, %3;" : "=l"(d) : "l"(a), "l"(b), "l"(c)); return d;
}
__device__ __forceinline__ u64 add2(u64 a, u64 b) {
    u64 d; asm("add.rn.f32x2 %0, %1, %2;" : "=l"(d) : "l"(a), "l"(b)); return d;
}

// ---------------------------------------------------------------------------
// Fused aux kernel (256 threads/block):
//   blocks 0..63   : 1024-pt RADIX-4 DIT FFT of softplus(H[r,:]) (5 stages)
//   blocks 64..127 : prep (softplus(W), theta, cos, sin) -> [r][n]
// ---------------------------------------------------------------------------
__global__ void __launch_bounds__(256) aux_kernel(
    const float* __restrict__ H, int nH,
    const float* __restrict__ W,
    const float* __restrict__ tau, int nWT)
{
    if (blockIdx.x >= RANK) {
        int base = (blockIdx.x - RANK) * 1024;
#pragma unroll
        for (int k = 0; k < 4; k++) {
            int i = base + k * 256 + threadIdx.x;
            float wv = (i < nWT) ? W[i]   : 0.0f;
            float tv = (i < nWT) ? tau[i] : 0.0f;
            int n = i >> 6;           // / RANK
            int r = i & (RANK - 1);
            float wp = __logf(1.0f + __expf(wv));
            float th = (float)(2.0 * M_PI / (double)MM) * tv;
            float s1, c1;
            __sincosf(th, &s1, &c1);
            d_prep[r * NN + n] = make_float4(wp, th, c1, s1);
        }
        return;
    }

    __shared__ float re[MM];
    __shared__ float im[MM];
    int r = blockIdx.x;

    for (int i = threadIdx.x; i < MM; i += 256) {
        int src = r * MM + i;
        float x = (src < nH) ? H[src] : 0.0f;
        float v = __logf(1.0f + __expf(x));
        int dr = 0, t = i;
#pragma unroll
        for (int d = 0; d < 5; d++) { dr = (dr << 2) | (t & 3); t >>= 2; }
        re[dr] = v;
        im[dr] = 0.0f;
    }
    __syncthreads();

    int q = 1;
#pragma unroll
    for (int s = 0; s < 5; s++) {
        int m = q << 2;
        int k = threadIdx.x;
        int gi = k / q;
        int j  = k - gi * q;
        int i0 = gi * m + j;
        int i1 = i0 + q, i2 = i1 + q, i3 = i2 + q;

        float ang = (-6.2831853071795865f / (float)m) * (float)j;
        float c1, s1, c2, s2;
        __sincosf(ang, &s1, &c1);
        __sincosf(2.0f * ang, &s2, &c2);
        float c3 = c1 * c2 - s1 * s2;
        float s3 = s1 * c2 + c1 * s2;

        float ar = re[i0], ai = im[i0];
        float br = re[i1], bi = im[i1];
        float cr = re[i2], ci = im[i2];
        float dr_ = re[i3], di = im[i3];

        float tbr = br * c1 - bi * s1, tbi = bi * c1 + br * s1;
        float tcr = cr * c2 - ci * s2, tci = ci * c2 + cr * s2;
        float tdr = dr_ * c3 - di * s3, tdi = di * c3 + dr_ * s3;

        float e0r = ar + tcr,  e0i = ai + tci;
        float e1r = ar - tcr,  e1i = ai - tci;
        float e2r = tbr + tdr, e2i = tbi + tdi;
        float e3r = tbr - tdr, e3i = tbi - tdi;

        re[i0] = e0r + e2r;  im[i0] = e0i + e2i;
        re[i1] = e1r + e3i;  im[i1] = e1i - e3r;
        re[i2] = e0r - e2r;  im[i2] = e0i - e2i;
        re[i3] = e1r - e3i;  im[i3] = e1i + e3r;
        __syncthreads();
        q = m;
    }

    for (int i = threadIdx.x; i < MM; i += 256)
        d_Hf[r * MM + i] = make_float2(re[i], im[i]);
}

// ---------------------------------------------------------------------------
// out[n,f] = Re( sum_r wp e^{-i theta f} Hf[r,f] ).
// Sign-transformed Chebyshev recurrence, f32x2-packed. This round: TWO
// independent r-chains interleaved per thread (2x ILP); regs capped at 84.
// ---------------------------------------------------------------------------
__global__ void __launch_bounds__(NTH, 3) main_kernel(float* __restrict__ outf,
                                                      int capf) {
    __shared__ ulonglong2 g[RANK][FCH / 2];  // .x = sg*(Re,Re'), .y = sg*(-Im,-Im')
    __shared__ u64 comb[3][NSL][FCH / 2];    // partials from r-quarters 1..3

    int c  = blockIdx.x;
    int f0 = c * FCH;
    int t  = threadIdx.x;
    int ln = t & (NSL - 1);          // n within slice
    int rq = t >> 6;                 // r-quarter: 0..3
    int n  = blockIdx.y * NSL + ln;

    for (int e = t; e < RANK * (FCH / 2); e += NTH) {
        int rr = e >> 3;             // / 8
        int tt = e & 7;
        float4 ab = *(const float4*)&d_Hf[rr * MM + f0 + 2 * tt];
        float sg = (tt & 2) ? -1.0f : 1.0f;          // sigma_t = (-1)^(t/2)
        g[rr][tt] = make_ulonglong2(pack2(sg * ab.x, sg * ab.z),
                                    pack2(-sg * ab.y, -sg * ab.w));
    }
    __syncthreads();

    u64 acc[FCH / 2];
#pragma unroll
    for (int q = 0; q < FCH / 2; q++) acc[q] = 0ull;

    const float f0f = (float)f0;
    const int rbeg = rq * RQ;
    const float4* prep = &d_prep[rbeg * NN + n];

    // Prefetch first pair.
    float4 pb[2];
#pragma unroll
    for (int k = 0; k < 2; k++) pb[k] = prep[k * NN];

    for (int r0 = 0; r0 < RQ; r0 += 2) {
        float4 pn[2];
        if (r0 + 2 < RQ) {
#pragma unroll
            for (int k = 0; k < 2; k++) pn[k] = prep[(r0 + 2 + k) * NN];
        }

        // Seeds for both chains.
        u64 Kp[2], Kn[2], qr_c[2], qi_c[2], qr_p[2], qi_p[2];
#pragma unroll
        for (int k = 0; k < 2; k++) {
            float wp = pb[k].x, th = pb[k].y, c1 = pb[k].z, s1 = pb[k].w;
            float s0, c0;
            __sincosf(th * f0f, &s0, &c0);

            float pr0 = wp * c0, pi0 = -wp * s0;              // p(f0)
            float pr1  = fmaf(pr0, c1,  pi0 * s1);            // p(f0+1)
            float pi1  = fmaf(pi0, c1, -pr0 * s1);
            float prm1 = fmaf(pr0, c1, -pi0 * s1);            // p(f0-1)
            float pim1 = fmaf(pi0, c1,  pr0 * s1);
            float prm2 = fmaf(prm1, c1, -pim1 * s1);          // p(f0-2)
            float pim2 = fmaf(pim1, c1,  prm1 * s1);
            float K    = fmaf(4.0f * c1, c1, -2.0f);          // 2 cos 2theta

            Kp[k] = bcast2(K);  Kn[k] = bcast2(-K);
            qr_c[k] = pack2(pr0, pr1);      qi_c[k] = pack2(pi0, pi1);
            qr_p[k] = pack2(-prm2, -prm1);  qi_p[k] = pack2(-pim2, -pim1);
        }

#pragma unroll
        for (int tt = 0; tt < FCH / 2; tt++) {
#pragma unroll
            for (int k = 0; k < 2; k++) {
                ulonglong2 gv = g[rbeg + r0 + k][tt];   // LDS.128 (broadcast)
                acc[tt] = fma2(qr_c[k], gv.x, acc[tt]);
                acc[tt] = fma2(qi_c[k], gv.y, acc[tt]);
                u64 Kt = (tt & 1) ? Kn[k] : Kp[k];
                u64 nr = fma2(Kt, qr_c[k], qr_p[k]);
                u64 ni = fma2(Kt, qi_c[k], qi_p[k]);
                qr_p[k] = qr_c[k];  qr_c[k] = nr;
                qi_p[k] = qi_c[k];  qi_c[k] = ni;
            }
        }

#pragma unroll
        for (int k = 0; k < 2; k++) pb[k] = pn[k];
    }

    // Combine the four r-quarters.
    if (rq) {
#pragma unroll
        for (int q = 0; q < FCH / 2; q++) comb[rq - 1][ln][q] = acc[q];
    }
    __syncthreads();
    if (rq) return;

#pragma unroll
    for (int q = 0; q < FCH / 2; q++) {
        acc[q] = add2(acc[q], comb[0][ln][q]);
        acc[q] = add2(acc[q], add2(comb[1][ln][q], comb[2][ln][q]));
    }

    int base = n * MM + f0;
    if (base + FCH <= capf) {
        float4* o4 = (float4*)(outf + base);       // 64B aligned
#pragma unroll
        for (int v = 0; v < FCH / 4; v++) {
            float a0, a1, b0, b1;
            unpack2(acc[2 * v],     a0, a1);
            unpack2(acc[2 * v + 1], b0, b1);
            o4[v] = make_float4(a0, a1, b0, b1);
        }
    } else {
#pragma unroll
        for (int q = 0; q < FCH / 2; q++) {
            float lo, hi;
            unpack2(acc[q], lo, hi);
            int o = base + 2 * q;
            if (o < capf)     outf[o]     = lo;
            if (o + 1 < capf) outf[o + 1] = hi;
        }
    }
}

// ---------------------------------------------------------------------------
extern "C" void kernel_launch(void* const* d_in, const int* in_sizes, int n_in,
                              void* d_out, int out_size) {
    if (n_in < 3) return;
    const float* W   = (const float*)d_in[0];
    const float* H   = (const float*)d_in[1];
    const float* tau = (const float*)d_in[2];
    float* outf = (float*)d_out;

    int nWT = in_sizes[0] < in_sizes[2] ? in_sizes[0] : in_sizes[2];
    aux_kernel<<<2 * RANK, 256>>>(H, in_sizes[1], W, tau, nWT);
    main_kernel<<<dim3(MM / FCH, NN / NSL), NTH>>>(outf, out_size);
}

// round 17
// speedup vs baseline: 1.2720x; 1.0932x over previous
#include <cuda_runtime.h>
#include <math.h>

#define NN   1024
#define RANK 64
#define MM   1024
#define FCH  16    // f per block (8 packed pairs)
#define NSL  64    // n-slice per block
#define NTH  256   // threads per block (4 r-quarters x 64 n)
#define RQ   (RANK / 4)   // r's per thread = 16

// Scratch
__device__ float2 d_Hf[RANK * MM];     // FFT(softplus(H)), [r][f]
__device__ float4 d_prep[RANK * NN];   // (wp, theta, cos th, sin th), [r][n]

typedef unsigned long long u64;

__device__ __forceinline__ u64 pack2(float lo, float hi) {
    u64 r; asm("mov.b64 %0, {%1, %2};" : "=l"(r) : "f"(lo), "f"(hi)); return r;
}
__device__ __forceinline__ u64 bcast2(float x) { return pack2(x, x); }
__device__ __forceinline__ void unpack2(u64 v, float& lo, float& hi) {
    asm("mov.b64 {%0, %1}, %2;" : "=f"(lo), "=f"(hi) : "l"(v));
}
__device__ __forceinline__ u64 fma2(u64 a, u64 b, u64 c) {
    u64 d; asm("fma.rn.f32x2 %0, %1, %2, %3;" : "=l"(d) : "l"(a), "l"(b), "l"(c)); return d;
}
__device__ __forceinline__ u64 add2(u64 a, u64 b) {
    u64 d; asm("add.rn.f32x2 %0, %1, %2;" : "=l"(d) : "l"(a), "l"(b)); return d;
}

// ---------------------------------------------------------------------------
// Fused aux kernel (256 threads/block):
//   blocks 0..63   : 1024-pt RADIX-4 DIT FFT of softplus(H[r,:]) (5 stages)
//   blocks 64..127 : prep (softplus(W), theta, cos, sin) -> [r][n]
// ---------------------------------------------------------------------------
__global__ void __launch_bounds__(256) aux_kernel(
    const float* __restrict__ H, int nH,
    const float* __restrict__ W,
    const float* __restrict__ tau, int nWT)
{
    if (blockIdx.x >= RANK) {
        int base = (blockIdx.x - RANK) * 1024;
#pragma unroll
        for (int k = 0; k < 4; k++) {
            int i = base + k * 256 + threadIdx.x;
            float wv = (i < nWT) ? W[i]   : 0.0f;
            float tv = (i < nWT) ? tau[i] : 0.0f;
            int n = i >> 6;           // / RANK
            int r = i & (RANK - 1);
            float wp = __logf(1.0f + __expf(wv));
            float th = (float)(2.0 * M_PI / (double)MM) * tv;
            float s1, c1;
            __sincosf(th, &s1, &c1);
            d_prep[r * NN + n] = make_float4(wp, th, c1, s1);
        }
        return;
    }

    __shared__ float re[MM];
    __shared__ float im[MM];
    int r = blockIdx.x;

    for (int i = threadIdx.x; i < MM; i += 256) {
        int src = r * MM + i;
        float x = (src < nH) ? H[src] : 0.0f;
        float v = __logf(1.0f + __expf(x));
        int dr = 0, t = i;
#pragma unroll
        for (int d = 0; d < 5; d++) { dr = (dr << 2) | (t & 3); t >>= 2; }
        re[dr] = v;
        im[dr] = 0.0f;
    }
    __syncthreads();

    int q = 1;
#pragma unroll
    for (int s = 0; s < 5; s++) {
        int m = q << 2;
        int k = threadIdx.x;
        int gi = k / q;
        int j  = k - gi * q;
        int i0 = gi * m + j;
        int i1 = i0 + q, i2 = i1 + q, i3 = i2 + q;

        float ang = (-6.2831853071795865f / (float)m) * (float)j;
        float c1, s1, c2, s2;
        __sincosf(ang, &s1, &c1);
        __sincosf(2.0f * ang, &s2, &c2);
        float c3 = c1 * c2 - s1 * s2;
        float s3 = s1 * c2 + c1 * s2;

        float ar = re[i0], ai = im[i0];
        float br = re[i1], bi = im[i1];
        float cr = re[i2], ci = im[i2];
        float dr_ = re[i3], di = im[i3];

        float tbr = br * c1 - bi * s1, tbi = bi * c1 + br * s1;
        float tcr = cr * c2 - ci * s2, tci = ci * c2 + cr * s2;
        float tdr = dr_ * c3 - di * s3, tdi = di * c3 + dr_ * s3;

        float e0r = ar + tcr,  e0i = ai + tci;
        float e1r = ar - tcr,  e1i = ai - tci;
        float e2r = tbr + tdr, e2i = tbi + tdi;
        float e3r = tbr - tdr, e3i = tbi - tdi;

        re[i0] = e0r + e2r;  im[i0] = e0i + e2i;
        re[i1] = e1r + e3i;  im[i1] = e1i - e3r;
        re[i2] = e0r - e2r;  im[i2] = e0i - e2i;
        re[i3] = e1r - e3i;  im[i3] = e1i + e3r;
        __syncthreads();
        q = m;
    }

    for (int i = threadIdx.x; i < MM; i += 256)
        d_Hf[r * MM + i] = make_float2(re[i], im[i]);
}

// ---------------------------------------------------------------------------
// out[n,f] = Re( sum_r wp e^{-i theta f} Hf[r,f] ).
// Sign-transformed Chebyshev recurrence, f32x2-packed. This round:
// 1-deep explicit shared-tile prefetch, Chebyshev-based seeds,
// griddepcontrol.wait for PDL overlap with the aux kernel.
// ---------------------------------------------------------------------------
__global__ void __launch_bounds__(NTH, 3) main_kernel(float* __restrict__ outf,
                                                      int capf) {
    __shared__ ulonglong2 g[RANK + 1][FCH / 2];  // +1 row pad for prefetch
    __shared__ u64 comb[3][NSL][FCH / 2];

    // PDL: wait for aux kernel's writes (no-op when launched without PDL).
    asm volatile("griddepcontrol.wait;" ::: "memory");

    int c  = blockIdx.x;
    int f0 = c * FCH;
    int t  = threadIdx.x;
    int ln = t & (NSL - 1);          // n within slice
    int rq = t >> 6;                 // r-quarter: 0..3
    int n  = blockIdx.y * NSL + ln;

    for (int e = t; e < RANK * (FCH / 2); e += NTH) {
        int rr = e >> 3;             // / 8
        int tt = e & 7;
        float4 ab = *(const float4*)&d_Hf[rr * MM + f0 + 2 * tt];
        float sg = (tt & 2) ? -1.0f : 1.0f;          // sigma_t = (-1)^(t/2)
        g[rr][tt] = make_ulonglong2(pack2(sg * ab.x, sg * ab.z),
                                    pack2(-sg * ab.y, -sg * ab.w));
    }
    __syncthreads();

    u64 acc[FCH / 2];
#pragma unroll
    for (int q = 0; q < FCH / 2; q++) acc[q] = 0ull;

    const float f0f = (float)f0;
    const int rbeg = rq * RQ;
    const float4* prep = &d_prep[rbeg * NN + n];
    const ulonglong2* gp = &g[rbeg][0];   // RQ rows contiguous (+pad row)

    float4 pb[2];
#pragma unroll
    for (int k = 0; k < 2; k++) pb[k] = prep[k * NN];

    ulonglong2 gv = gp[0];               // rolling prefetched tile value

    for (int r0 = 0; r0 < RQ; r0 += 2) {
        float4 pn[2];
        if (r0 + 2 < RQ) {
#pragma unroll
            for (int k = 0; k < 2; k++) pn[k] = prep[(r0 + 2 + k) * NN];
        }

#pragma unroll
        for (int k = 0; k < 2; k++) {
            float wp = pb[k].x, th = pb[k].y, c1 = pb[k].z, s1 = pb[k].w;

            float s0, c0;
            __sincosf(th * f0f, &s0, &c0);           // start angle (<= ~6.2)

            float tc   = c1 + c1;                    // 2 cos theta
            float pr0  = wp * c0,  pi0 = -wp * s0;            // p(f0)
            float prm1 = fmaf(pr0, c1, -pi0 * s1);            // p(f0-1)
            float pim1 = fmaf(pi0, c1,  pr0 * s1);
            float pr1  = fmaf(tc, pr0, -prm1);                // p(f0+1) Cheb
            float pi1  = fmaf(tc, pi0, -pim1);
            float prm2 = fmaf(tc, prm1, -pr0);                // p(f0-2) Cheb
            float pim2 = fmaf(tc, pim1, -pi0);
            float K    = fmaf(tc, tc, -2.0f);                 // 2 cos 2theta

            u64 Kp = bcast2(K), Kn = bcast2(-K);
            u64 qr_c = pack2(pr0, pr1),     qi_c = pack2(pi0, pi1);
            u64 qr_p = pack2(-prm2, -prm1), qi_p = pack2(-pim2, -pim1);

            int base = (r0 + k) * (FCH / 2);
#pragma unroll
            for (int tt = 0; tt < FCH / 2; tt++) {
                ulonglong2 gn = gp[base + tt + 1];   // prefetch next (pad-safe)
                acc[tt] = fma2(qr_c, gv.x, acc[tt]);
                acc[tt] = fma2(qi_c, gv.y, acc[tt]);
                u64 Kt = (tt & 1) ? Kn : Kp;
                u64 nr = fma2(Kt, qr_c, qr_p);
                u64 ni = fma2(Kt, qi_c, qi_p);
                qr_p = qr_c;  qr_c = nr;
                qi_p = qi_c;  qi_c = ni;
                gv = gn;
            }
        }

#pragma unroll
        for (int k = 0; k < 2; k++) pb[k] = pn[k];
    }

    if (rq) {
#pragma unroll
        for (int q = 0; q < FCH / 2; q++) comb[rq - 1][ln][q] = acc[q];
    }
    __syncthreads();
    if (rq) return;

#pragma unroll
    for (int q = 0; q < FCH / 2; q++) {
        acc[q] = add2(acc[q], comb[0][ln][q]);
        acc[q] = add2(acc[q], add2(comb[1][ln][q], comb[2][ln][q]));
    }

    int base = n * MM + f0;
    if (base + FCH <= capf) {
        float4* o4 = (float4*)(outf + base);
#pragma unroll
        for (int v = 0; v < FCH / 4; v++) {
            float a0, a1, b0, b1;
            unpack2(acc[2 * v],     a0, a1);
            unpack2(acc[2 * v + 1], b0, b1);
            o4[v] = make_float4(a0, a1, b0, b1);
        }
    } else {
#pragma unroll
        for (int q = 0; q < FCH / 2; q++) {
            float lo, hi;
            unpack2(acc[q], lo, hi);
            int o = base + 2 * q;
            if (o < capf)     outf[o]     = lo;
            if (o + 1 < capf) outf[o + 1] = hi;
        }
    }
}

// ---------------------------------------------------------------------------
extern "C" void kernel_launch(void* const* d_in, const int* in_sizes, int n_in,
                              void* d_out, int out_size) {
    if (n_in < 3) return;
    const float* W   = (const float*)d_in[0];
    const float* H   = (const float*)d_in[1];
    const float* tau = (const float*)d_in[2];
    float* outf = (float*)d_out;

    int nWT = in_sizes[0] < in_sizes[2] ? in_sizes[0] : in_sizes[2];
    aux_kernel<<<2 * RANK, 256>>>(H, in_sizes[1], W, tau, nWT);

    dim3 grid(MM / FCH, NN / NSL);

    // PDL path only when the per-thread default stream is being captured
    // (the harness compiles with per-thread default stream; plain <<<>>>
    // launches land on it). Otherwise launch plainly.
    cudaStreamCaptureStatus st = cudaStreamCaptureStatusNone;
    cudaStreamIsCapturing(cudaStreamPerThread, &st);
    if (st == cudaStreamCaptureStatusActive) {
        cudaLaunchConfig_t cfg = {};
        cfg.gridDim = grid;
        cfg.blockDim = dim3(NTH, 1, 1);
        cfg.dynamicSmemBytes = 0;
        cfg.stream = cudaStreamPerThread;
        cudaLaunchAttribute attr[1];
        attr[0].id = cudaLaunchAttributeProgrammaticStreamSerialization;
        attr[0].val.programmaticStreamSerializationAllowed = 1;
        cfg.attrs = attr;
        cfg.numAttrs = 1;
        cudaLaunchKernelEx(&cfg, main_kernel, outf, out_size);
    } else {
        main_kernel<<<grid, NTH>>>(outf, out_size);
    }
}